// round 16
// baseline (speedup 1.0000x reference)
#include <cuda_runtime.h>
#include <cuda_fp16.h>
#include <cstdint>
#include <math.h>

// ---------------------------------------------------------------------------
// Problem dims
// ---------------------------------------------------------------------------
#define BB      16
#define SS      512
#define DMODEL  1024
#define NHEADS  16
#define DK      64
#define DFF     4096
#define MROWS   (BB * SS)          // 8192
#define MEG     (1024 * 1024)
#define QKVN    3072

// ---------------------------------------------------------------------------
// Scratch (device globals)
// ---------------------------------------------------------------------------
__device__ float  g_x2 [MROWS * DMODEL];
__device__ __half g_ln [MROWS * DMODEL];
__device__ __half g_att[MROWS * DMODEL];
__device__ __half g_qkv[MROWS * QKVN];       // q pre-scaled 1/8
__device__ __half g_ff [MROWS * DFF];
__device__ __half g_w  [12 * MEG];           // transposed fp16 weights [N][K]
// offsets: Wq=0 (x0.125), Wk=1M, Wv=2M, Wo=3M, W1t=4M, W2t=8M

extern __shared__ char smem_raw[];

// ---------------------------------------------------------------------------
// PTX helpers
// ---------------------------------------------------------------------------
__device__ __forceinline__ uint32_t smem_u32(const void* p) {
    uint32_t a;
    asm("{ .reg .u64 t; cvta.to.shared.u64 t, %1; cvt.u32.u64 %0, t; }"
        : "=r"(a) : "l"(p));
    return a;
}
#define CP_ASYNC16(dst, src) \
    asm volatile("cp.async.cg.shared.global [%0], [%1], 16;" :: "r"(dst), "l"(src))
#define CP_COMMIT() asm volatile("cp.async.commit_group;" ::: "memory")
#define CP_WAIT(n)  asm volatile("cp.async.wait_group %0;" :: "n"(n) : "memory")

#define LDMATRIX_X4(r0, r1, r2, r3, addr) \
    asm volatile("ldmatrix.sync.aligned.m8n8.x4.shared.b16 {%0,%1,%2,%3}, [%4];" \
                 : "=r"(r0), "=r"(r1), "=r"(r2), "=r"(r3) : "r"(addr))
#define LDMATRIX_X4_T(r0, r1, r2, r3, addr) \
    asm volatile("ldmatrix.sync.aligned.m8n8.x4.trans.shared.b16 {%0,%1,%2,%3}, [%4];" \
                 : "=r"(r0), "=r"(r1), "=r"(r2), "=r"(r3) : "r"(addr))

#define MMA_FP16(c0, c1, c2, c3, a0, a1, a2, a3, b0, b1) \
    asm volatile("mma.sync.aligned.m16n8k16.row.col.f32.f16.f16.f32 " \
                 "{%0,%1,%2,%3}, {%4,%5,%6,%7}, {%8,%9}, {%0,%1,%2,%3};" \
                 : "+f"(c0), "+f"(c1), "+f"(c2), "+f"(c3) \
                 : "r"(a0), "r"(a1), "r"(a2), "r"(a3), "r"(b0), "r"(b1))

__device__ __forceinline__ uint32_t pack2h(__half x, __half y) {
    return (uint32_t)__half_as_ushort(x) |
           ((uint32_t)__half_as_ushort(y) << 16);
}

// ---------------------------------------------------------------------------
// LayerNorm row -> fp16 (device helper, 256 threads)
// ---------------------------------------------------------------------------
__device__ __forceinline__ void layernorm_row(
    const float* __restrict__ x, const float* __restrict__ g,
    const float* __restrict__ be, __half* __restrict__ o, int row,
    float* sm1, float* sm2)
{
    const int tid = threadIdx.x;
    const float4 v = *(const float4*)(x + (size_t)row * DMODEL + tid * 4);

    float s1 = v.x + v.y + v.z + v.w;
    float s2 = v.x * v.x + v.y * v.y + v.z * v.z + v.w * v.w;
    #pragma unroll
    for (int off = 16; off > 0; off >>= 1) {
        s1 += __shfl_xor_sync(0xffffffffu, s1, off);
        s2 += __shfl_xor_sync(0xffffffffu, s2, off);
    }
    const int w = tid >> 5, l = tid & 31;
    if (l == 0) { sm1[w] = s1; sm2[w] = s2; }
    __syncthreads();
    if (w == 0) {
        s1 = (l < 8) ? sm1[l] : 0.f;
        s2 = (l < 8) ? sm2[l] : 0.f;
        #pragma unroll
        for (int off = 4; off > 0; off >>= 1) {
            s1 += __shfl_xor_sync(0xffffffffu, s1, off);
            s2 += __shfl_xor_sync(0xffffffffu, s2, off);
        }
        if (l == 0) { sm1[0] = s1; sm2[0] = s2; }
    }
    __syncthreads();

    const float mu  = sm1[0] * (1.f / DMODEL);
    const float var = sm2[0] * (1.f / DMODEL) - mu * mu;
    const float inv = rsqrtf(var + 1e-5f);

    const float4 gv = *(const float4*)(g  + tid * 4);
    const float4 bv = *(const float4*)(be + tid * 4);
    __align__(8) __half h4[4];
    h4[0] = __float2half((v.x - mu) * inv * gv.x + bv.x);
    h4[1] = __float2half((v.y - mu) * inv * gv.y + bv.y);
    h4[2] = __float2half((v.z - mu) * inv * gv.z + bv.z);
    h4[3] = __float2half((v.w - mu) * inv * gv.w + bv.w);
    *(uint2*)(o + (size_t)row * DMODEL + tid * 4) = *(uint2*)h4;
}

__global__ void __launch_bounds__(256) layernorm_fp16_kernel(
    const float* __restrict__ x, const float* __restrict__ g,
    const float* __restrict__ be, __half* __restrict__ o)
{
    __shared__ float sm1[8], sm2[8];
    layernorm_row(x, g, be, o, blockIdx.x, sm1, sm2);
}

// ---------------------------------------------------------------------------
// FUSED prologue: blocks [0,12288) weight transpose; [12288,20480) LN1 rows
// ---------------------------------------------------------------------------
__global__ void __launch_bounds__(256) prologue_kernel(
    const float* __restrict__ Wq, const float* __restrict__ Wk,
    const float* __restrict__ Wv, const float* __restrict__ Wo,
    const float* __restrict__ W1, const float* __restrict__ W2,
    __half* __restrict__ wgt,
    const float* __restrict__ x, const float* __restrict__ g1,
    const float* __restrict__ be1, __half* __restrict__ ln)
{
    const int t = blockIdx.x;
    if (t >= 12288) {
        __shared__ float sm1[8], sm2[8];
        layernorm_row(x, g1, be1, ln, t - 12288, sm1, sm2);
        return;
    }

    const float* W; __half* o; int K, N, local; float scale = 1.f;
    if (t < 1024)      { W = Wq; o = wgt;           K = 1024; N = 1024; local = t;        scale = 0.125f; }
    else if (t < 2048) { W = Wk; o = wgt + 1 * MEG; K = 1024; N = 1024; local = t - 1024; }
    else if (t < 3072) { W = Wv; o = wgt + 2 * MEG; K = 1024; N = 1024; local = t - 2048; }
    else if (t < 4096) { W = Wo; o = wgt + 3 * MEG; K = 1024; N = 1024; local = t - 3072; }
    else if (t < 8192) { W = W1; o = wgt + 4 * MEG; K = 1024; N = 4096; local = t - 4096; }
    else               { W = W2; o = wgt + 8 * MEG; K = 4096; N = 1024; local = t - 8192; }

    const int ntn = N >> 5;
    const int n0 = (local % ntn) * 32;
    const int k0 = (local / ntn) * 32;

    __shared__ float tb[32][33];
    const int tx = threadIdx.x & 31, ty = threadIdx.x >> 5;
    #pragma unroll
    for (int j = 0; j < 32; j += 8)
        tb[ty + j][tx] = W[(size_t)(k0 + ty + j) * N + n0 + tx];
    __syncthreads();
    #pragma unroll
    for (int j = 0; j < 32; j += 8)
        o[(size_t)(n0 + ty + j) * K + k0 + tx] = __float2half(tb[tx][ty + j] * scale);
}

// ---------------------------------------------------------------------------
// fp16 mma.sync GEMM: CTA tile 128x128, BK=64, 2-stage cp.async,
// SIXTEEN warps (512 threads), warp tile 32x32 (warps 4m x 4n).
// acc 32 regs -> <=64 regs/thread -> 2 CTA/SM = 32 warps/SM (44% occ).
// MODE: 0 = fp16 plain | 1 = f32 +res | 2 = fp16 relu(+bias) | 3 = f32 +bias +res
// ---------------------------------------------------------------------------
#define SM_STRIDE 72
#define SM_STRB   (SM_STRIDE * 2)
#define TILE_B    (128 * SM_STRB)          // 18432
#define STAGE_B   (2 * TILE_B)             // 36864

template<int MODE>
__global__ void __launch_bounds__(512, 2) gemm_fp16_kernel(
    const __half* __restrict__ A, const __half* __restrict__ B,
    const float* __restrict__ bias, const float* __restrict__ res,
    float* __restrict__ Cf, __half* __restrict__ Oh, int M, int N, int K)
{
    const uint32_t sbase = smem_u32(smem_raw);
    const int tid = threadIdx.x;
    const int wid = tid >> 5, lid = tid & 31;
    const int warp_m = wid & 3;          // 4 x 32 rows
    const int warp_n = wid >> 2;         // 4 x 32 cols
    const int bm = blockIdx.y * 128;
    const int bn = blockIdx.x * 128;

    const int segN = K >> 6;
    const __half* Ag0 = A + (size_t)bm * K;
    const __half* Bg0 = B + (size_t)bn * K;

    auto load_chunk = [&](int c) {
        const uint32_t st = sbase + (c & 1) * STAGE_B;
        const int kk = c << 6;
        const __half* Ag = Ag0 + kk;
        const __half* Bg = Bg0 + kk;
        #pragma unroll
        for (int i = 0; i < 2; i++) {
            const int e = tid + 512 * i;       // 0..1023
            const int r = e >> 3;
            const int cch = e & 7;
            CP_ASYNC16(st + r * SM_STRB + cch * 16,
                       (const void*)(Ag + (size_t)r * K + cch * 8));
            CP_ASYNC16(st + TILE_B + r * SM_STRB + cch * 16,
                       (const void*)(Bg + (size_t)r * K + cch * 8));
        }
        CP_COMMIT();
    };

    float acc[2][4][4];
    #pragma unroll
    for (int mi = 0; mi < 2; mi++)
        #pragma unroll
        for (int ni = 0; ni < 4; ni++)
            #pragma unroll
            for (int q = 0; q < 4; q++) acc[mi][ni][q] = 0.f;

    const int a_row_off = (lid & 7) + ((lid >> 3) & 1) * 8;
    const int a_k_off   = ((lid >> 4) & 1) * 8;
    const int b_n_off   = (lid & 7) + ((lid >> 4) & 1) * 8;
    const int b_k_off   = ((lid >> 3) & 1) * 8;

    load_chunk(0);

    for (int c = 0; c < segN; c++) {
        if (c + 1 < segN) load_chunk(c + 1);
        if (c + 1 < segN) { CP_WAIT(1); } else { CP_WAIT(0); }
        __syncthreads();

        const uint32_t sA = sbase + (c & 1) * STAGE_B;
        const uint32_t sB = sA + TILE_B;

        #pragma unroll
        for (int k16 = 0; k16 < 64; k16 += 16) {
            uint32_t a[2][4];
            #pragma unroll
            for (int mi = 0; mi < 2; mi++) {
                const uint32_t roff =
                    (warp_m * 32 + mi * 16 + a_row_off) * SM_STRB + (k16 + a_k_off) * 2;
                LDMATRIX_X4(a[mi][0], a[mi][1], a[mi][2], a[mi][3], sA + roff);
            }
            uint32_t b[4][2];
            #pragma unroll
            for (int np = 0; np < 2; np++) {
                const uint32_t roff =
                    (warp_n * 32 + np * 16 + b_n_off) * SM_STRB + (k16 + b_k_off) * 2;
                uint32_t r0, r1, r2, r3;
                LDMATRIX_X4(r0, r1, r2, r3, sB + roff);
                b[2 * np][0] = r0; b[2 * np][1] = r1;
                b[2 * np + 1][0] = r2; b[2 * np + 1][1] = r3;
            }
            #pragma unroll
            for (int mi = 0; mi < 2; mi++)
                #pragma unroll
                for (int ni = 0; ni < 4; ni++)
                    MMA_FP16(acc[mi][ni][0], acc[mi][ni][1],
                             acc[mi][ni][2], acc[mi][ni][3],
                             a[mi][0], a[mi][1], a[mi][2], a[mi][3],
                             b[ni][0], b[ni][1]);
        }
        __syncthreads();
    }

    const int lr = lid >> 2;
    const int lc = (lid & 3) * 2;
    #pragma unroll
    for (int mi = 0; mi < 2; mi++) {
        #pragma unroll
        for (int ni = 0; ni < 4; ni++) {
            const int col = bn + warp_n * 32 + ni * 8 + lc;
            #pragma unroll
            for (int half = 0; half < 2; half++) {
                const int row = bm + warp_m * 32 + mi * 16 + lr + half * 8;
                const size_t off = (size_t)row * N + col;
                float v0 = acc[mi][ni][2 * half];
                float v1 = acc[mi][ni][2 * half + 1];
                if (MODE == 0) {
                    *(uint32_t*)(Oh + off) =
                        pack2h(__float2half(v0), __float2half(v1));
                } else if (MODE == 2) {
                    v0 = fmaxf(v0 + bias[col], 0.f);
                    v1 = fmaxf(v1 + bias[col + 1], 0.f);
                    *(uint32_t*)(Oh + off) =
                        pack2h(__float2half(v0), __float2half(v1));
                } else {
                    if (MODE == 3) { v0 += bias[col]; v1 += bias[col + 1]; }
                    const float2 rr = *(const float2*)(res + off);
                    v0 += rr.x; v1 += rr.y;
                    *(float2*)(Cf + off) = make_float2(v0, v1);
                }
            }
        }
    }
}

// ---------------------------------------------------------------------------
// fp16 tensor-core causal flash attention (round-13 version, unchanged)
// ---------------------------------------------------------------------------
#define ATT_STR  72
#define ATT_STRB (ATT_STR * 2)
#define ATT_Q_B  (128 * ATT_STRB)
#define ATT_KV_B (64 * ATT_STRB)
#define ATT_ST_B (2 * ATT_KV_B)

__global__ void __launch_bounds__(256) attention_fp16_kernel(
    const __half* __restrict__ QKV, __half* __restrict__ O)
{
    const uint32_t sbase = smem_u32(smem_raw);
    const uint32_t sQ = sbase;

    const int qt = (int)gridDim.x - 1 - (int)blockIdx.x;   // heavy tiles first
    const int bh = blockIdx.y;
    const int b  = bh >> 4;
    const int h  = bh & 15;
    const int q0 = qt * 128;
    const size_t rowbase = (size_t)b * SS;

    const int tid = threadIdx.x;
    const int w   = tid >> 5;
    const int lid = tid & 31;
    const int lr  = lid >> 2;
    const int lq  = lid & 3;

    const int a_row_off = (lid & 7) + ((lid >> 3) & 1) * 8;
    const int a_k_off   = ((lid >> 4) & 1) * 8;
    const int b_n_off   = (lid & 7) + ((lid >> 4) & 1) * 8;
    const int b_k_off   = ((lid >> 3) & 1) * 8;
    const int v_row_off = (lid & 7) + ((lid >> 3) & 1) * 8;
    const int v_col_off = ((lid >> 4) & 1) * 8;

    // Q load: pure cp.async (Wq pre-scaled by 0.125)
    {
        const size_t qcol = (size_t)h * DK;
        #pragma unroll
        for (int i = 0; i < 4; i++) {
            const int e = tid + 256 * i;
            const int r = e >> 3;
            const int c = e & 7;
            CP_ASYNC16(sQ + r * ATT_STRB + c * 16,
                       (const void*)(QKV + (rowbase + q0 + r) * QKVN + qcol + c * 8));
        }
        CP_COMMIT();
    }

    auto kv_load = [&](int kt) {
        const uint32_t st = sbase + ATT_Q_B + (kt & 1) * ATT_ST_B;
        const size_t kcol = 1024 + (size_t)h * DK;
        const size_t vcol = 2048 + (size_t)h * DK;
        #pragma unroll
        for (int i = 0; i < 2; i++) {
            const int e = tid + 256 * i;
            const int r = e >> 3;
            const int c = e & 7;
            const size_t grow = (rowbase + kt * 64 + r) * QKVN;
            const uint32_t sm = r * ATT_STRB + c * 16;
            CP_ASYNC16(st + sm,            (const void*)(QKV + grow + kcol + c * 8));
            CP_ASYNC16(st + ATT_KV_B + sm, (const void*)(QKV + grow + vcol + c * 8));
        }
        CP_COMMIT();
    };

    float m0 = -1e30f, m1 = -1e30f, l0 = 0.f, l1 = 0.f;
    float o[8][4];
    #pragma unroll
    for (int ni = 0; ni < 8; ni++)
        #pragma unroll
        for (int q = 0; q < 4; q++) o[ni][q] = 0.f;

    const int NT = 2 * qt + 2;
    kv_load(0);

    for (int kt = 0; kt < NT; kt++) {
        if (kt + 1 < NT) kv_load(kt + 1);
        if (kt + 1 < NT) { CP_WAIT(1); } else { CP_WAIT(0); }
        __syncthreads();

        const int wrow_min = q0 + w * 16;
        if (64 * kt <= wrow_min + 15) {
            const uint32_t sK = sbase + ATT_Q_B + (kt & 1) * ATT_ST_B;
            const uint32_t sV = sK + ATT_KV_B;

            float s[8][4];
            #pragma unroll
            for (int ni = 0; ni < 8; ni++)
                #pragma unroll
                for (int q = 0; q < 4; q++) s[ni][q] = 0.f;

            #pragma unroll
            for (int k16 = 0; k16 < 64; k16 += 16) {
                uint32_t a0, a1, a2, a3;
                LDMATRIX_X4(a0, a1, a2, a3,
                    sQ + (w * 16 + a_row_off) * ATT_STRB + (k16 + a_k_off) * 2);
                uint32_t bb[8][2];
                #pragma unroll
                for (int np = 0; np < 4; np++) {
                    uint32_t r0, r1, r2, r3;
                    LDMATRIX_X4(r0, r1, r2, r3,
                        sK + (np * 16 + b_n_off) * ATT_STRB + (k16 + b_k_off) * 2);
                    bb[2 * np][0] = r0; bb[2 * np][1] = r1;
                    bb[2 * np + 1][0] = r2; bb[2 * np + 1][1] = r3;
                }
                #pragma unroll
                for (int ni = 0; ni < 8; ni++)
                    MMA_FP16(s[ni][0], s[ni][1], s[ni][2], s[ni][3],
                             a0, a1, a2, a3, bb[ni][0], bb[ni][1]);
            }

            if (64 * kt + 63 > wrow_min) {
                const int r0g = wrow_min + lr;
                const int r1g = r0g + 8;
                #pragma unroll
                for (int ni = 0; ni < 8; ni++) {
                    const int c0 = 64 * kt + ni * 8 + lq * 2;
                    if (c0 > r0g)     s[ni][0] = -1e30f;
                    if (c0 + 1 > r0g) s[ni][1] = -1e30f;
                    if (c0 > r1g)     s[ni][2] = -1e30f;
                    if (c0 + 1 > r1g) s[ni][3] = -1e30f;
                }
            }

            float mt0 = -1e30f, mt1 = -1e30f;
            #pragma unroll
            for (int ni = 0; ni < 8; ni++) {
                mt0 = fmaxf(mt0, fmaxf(s[ni][0], s[ni][1]));
                mt1 = fmaxf(mt1, fmaxf(s[ni][2], s[ni][3]));
            }
            mt0 = fmaxf(mt0, __shfl_xor_sync(0xffffffffu, mt0, 1));
            mt0 = fmaxf(mt0, __shfl_xor_sync(0xffffffffu, mt0, 2));
            mt1 = fmaxf(mt1, __shfl_xor_sync(0xffffffffu, mt1, 1));
            mt1 = fmaxf(mt1, __shfl_xor_sync(0xffffffffu, mt1, 2));
            const float mn0 = fmaxf(m0, mt0), mn1 = fmaxf(m1, mt1);
            const float cr0 = __expf(m0 - mn0), cr1 = __expf(m1 - mn1);
            float rs0 = 0.f, rs1 = 0.f;
            #pragma unroll
            for (int ni = 0; ni < 8; ni++) {
                s[ni][0] = __expf(s[ni][0] - mn0); rs0 += s[ni][0];
                s[ni][1] = __expf(s[ni][1] - mn0); rs0 += s[ni][1];
                s[ni][2] = __expf(s[ni][2] - mn1); rs1 += s[ni][2];
                s[ni][3] = __expf(s[ni][3] - mn1); rs1 += s[ni][3];
            }
            rs0 += __shfl_xor_sync(0xffffffffu, rs0, 1);
            rs0 += __shfl_xor_sync(0xffffffffu, rs0, 2);
            rs1 += __shfl_xor_sync(0xffffffffu, rs1, 1);
            rs1 += __shfl_xor_sync(0xffffffffu, rs1, 2);
            l0 = l0 * cr0 + rs0;  l1 = l1 * cr1 + rs1;
            m0 = mn0;  m1 = mn1;
            #pragma unroll
            for (int ni = 0; ni < 8; ni++) {
                o[ni][0] *= cr0; o[ni][1] *= cr0;
                o[ni][2] *= cr1; o[ni][3] *= cr1;
            }

            #pragma unroll
            for (int j = 0; j < 4; j++) {
                const int t0 = 2 * j, t1 = 2 * j + 1;
                const uint32_t a0 = pack2h(__float2half(s[t0][0]), __float2half(s[t0][1]));
                const uint32_t a1 = pack2h(__float2half(s[t0][2]), __float2half(s[t0][3]));
                const uint32_t a2 = pack2h(__float2half(s[t1][0]), __float2half(s[t1][1]));
                const uint32_t a3 = pack2h(__float2half(s[t1][2]), __float2half(s[t1][3]));
                #pragma unroll
                for (int np = 0; np < 4; np++) {
                    uint32_t b0, b1, b2, b3;
                    LDMATRIX_X4_T(b0, b1, b2, b3,
                        sV + (j * 16 + v_row_off) * ATT_STRB + (np * 16 + v_col_off) * 2);
                    MMA_FP16(o[2*np][0], o[2*np][1], o[2*np][2], o[2*np][3],
                             a0, a1, a2, a3, b0, b1);
                    MMA_FP16(o[2*np+1][0], o[2*np+1][1], o[2*np+1][2], o[2*np+1][3],
                             a0, a1, a2, a3, b2, b3);
                }
            }
        }
        __syncthreads();
    }

    const float inv0 = 1.f / l0, inv1 = 1.f / l1;
    #pragma unroll
    for (int ni = 0; ni < 8; ni++) {
        const int col = h * DK + ni * 8 + lq * 2;
        {
            const size_t off = (rowbase + q0 + w * 16 + lr) * DMODEL + col;
            *(uint32_t*)(O + off) = pack2h(__float2half(o[ni][0] * inv0),
                                           __float2half(o[ni][1] * inv0));
        }
        {
            const size_t off = (rowbase + q0 + w * 16 + lr + 8) * DMODEL + col;
            *(uint32_t*)(O + off) = pack2h(__float2half(o[ni][2] * inv1),
                                           __float2half(o[ni][3] * inv1));
        }
    }
}

// ---------------------------------------------------------------------------
// Launch
// ---------------------------------------------------------------------------
extern "C" void kernel_launch(void* const* d_in, const int* in_sizes, int n_in,
                              void* d_out, int out_size)
{
    const float* x   = (const float*)d_in[0];
    const float* Wq  = (const float*)d_in[1];
    const float* Wk  = (const float*)d_in[2];
    const float* Wv  = (const float*)d_in[3];
    const float* Wo  = (const float*)d_in[4];
    const float* W1  = (const float*)d_in[5];
    const float* b1  = (const float*)d_in[6];
    const float* W2  = (const float*)d_in[7];
    const float* b2  = (const float*)d_in[8];
    const float* g1  = (const float*)d_in[9];
    const float* be1 = (const float*)d_in[10];
    const float* g2  = (const float*)d_in[11];
    const float* be2 = (const float*)d_in[12];
    float* out = (float*)d_out;

    float *x2;
    __half *ln, *att, *qkv, *ff, *wgt;
    cudaGetSymbolAddress((void**)&x2,  g_x2);
    cudaGetSymbolAddress((void**)&ln,  g_ln);
    cudaGetSymbolAddress((void**)&att, g_att);
    cudaGetSymbolAddress((void**)&qkv, g_qkv);
    cudaGetSymbolAddress((void**)&ff,  g_ff);
    cudaGetSymbolAddress((void**)&wgt, g_w);

    const int GEMM_SMEM = 2 * STAGE_B;                 // 73728
    cudaFuncSetAttribute(gemm_fp16_kernel<0>, cudaFuncAttributeMaxDynamicSharedMemorySize, GEMM_SMEM);
    cudaFuncSetAttribute(gemm_fp16_kernel<1>, cudaFuncAttributeMaxDynamicSharedMemorySize, GEMM_SMEM);
    cudaFuncSetAttribute(gemm_fp16_kernel<2>, cudaFuncAttributeMaxDynamicSharedMemorySize, GEMM_SMEM);
    cudaFuncSetAttribute(gemm_fp16_kernel<3>, cudaFuncAttributeMaxDynamicSharedMemorySize, GEMM_SMEM);
    const int ATTN_SMEM = ATT_Q_B + 2 * ATT_ST_B;      // 55296
    cudaFuncSetAttribute(attention_fp16_kernel, cudaFuncAttributeMaxDynamicSharedMemorySize, ATTN_SMEM);

    // 0) fused prologue: ALL weight transposes + LN1 in ONE launch
    prologue_kernel<<<12288 + MROWS, 256>>>(Wq, Wk, Wv, Wo, W1, W2, wgt,
                                            x, g1, be1, ln);

    // 1) fused QKV projection -> fp16 [row][3072]
    {
        dim3 grid(QKVN / 128, MROWS / 128);
        gemm_fp16_kernel<0><<<grid, 512, GEMM_SMEM>>>(ln, wgt,
            nullptr, nullptr, nullptr, qkv, MROWS, QKVN, DMODEL);
    }

    // 2) causal attention -> att (fp16), heavy q-tiles scheduled first
    {
        dim3 grid(SS / 128, BB * NHEADS);
        attention_fp16_kernel<<<grid, 256, ATTN_SMEM>>>(qkv, att);
    }

    // 3) output projection + residual(x) -> x2 (f32)
    {
        dim3 grid(DMODEL / 128, MROWS / 128);
        gemm_fp16_kernel<1><<<grid, 512, GEMM_SMEM>>>(att, wgt + 3 * MEG,
            nullptr, x, x2, nullptr, MROWS, DMODEL, DMODEL);
    }

    // 4) LN2 -> fp16
    layernorm_fp16_kernel<<<MROWS, 256>>>(x2, g2, be2, ln);

    // 5) FFN1: relu(h2 @ W1 + b1) -> fp16
    {
        dim3 grid(DFF / 128, MROWS / 128);
        gemm_fp16_kernel<2><<<grid, 512, GEMM_SMEM>>>(ln, wgt + 4 * MEG,
            b1, nullptr, nullptr, ff, MROWS, DFF, DMODEL);
    }

    // 6) FFN2: ff @ W2 + b2 + x2 -> out
    {
        dim3 grid(DMODEL / 128, MROWS / 128);
        gemm_fp16_kernel<3><<<grid, 512, GEMM_SMEM>>>(ff, wgt + 8 * MEG,
            b2, x2, out, nullptr, MROWS, DMODEL, DFF);
    }
}

// round 17
// speedup vs baseline: 1.0871x; 1.0871x over previous
#include <cuda_runtime.h>
#include <cuda_fp16.h>
#include <cstdint>
#include <math.h>

// ---------------------------------------------------------------------------
// Problem dims
// ---------------------------------------------------------------------------
#define BB      16
#define SS      512
#define DMODEL  1024
#define NHEADS  16
#define DK      64
#define DFF     4096
#define MROWS   (BB * SS)          // 8192
#define MEG     (1024 * 1024)
#define QKVN    3072

// ---------------------------------------------------------------------------
// Scratch (device globals)
// ---------------------------------------------------------------------------
__device__ float  g_x2 [MROWS * DMODEL];
__device__ __half g_ln [MROWS * DMODEL];
__device__ __half g_att[MROWS * DMODEL];
__device__ __half g_qkv[MROWS * QKVN];       // q pre-scaled 1/8
__device__ __half g_ff [MROWS * DFF];
__device__ __half g_w  [12 * MEG];           // transposed fp16 weights [N][K]
// offsets: Wq=0 (x0.125), Wk=1M, Wv=2M, Wo=3M, W1t=4M, W2t=8M

extern __shared__ char smem_raw[];

// ---------------------------------------------------------------------------
// PTX helpers
// ---------------------------------------------------------------------------
__device__ __forceinline__ uint32_t smem_u32(const void* p) {
    uint32_t a;
    asm("{ .reg .u64 t; cvta.to.shared.u64 t, %1; cvt.u32.u64 %0, t; }"
        : "=r"(a) : "l"(p));
    return a;
}
#define CP_ASYNC16(dst, src) \
    asm volatile("cp.async.cg.shared.global [%0], [%1], 16;" :: "r"(dst), "l"(src))
#define CP_COMMIT() asm volatile("cp.async.commit_group;" ::: "memory")
#define CP_WAIT(n)  asm volatile("cp.async.wait_group %0;" :: "n"(n) : "memory")

#define LDMATRIX_X4(r0, r1, r2, r3, addr) \
    asm volatile("ldmatrix.sync.aligned.m8n8.x4.shared.b16 {%0,%1,%2,%3}, [%4];" \
                 : "=r"(r0), "=r"(r1), "=r"(r2), "=r"(r3) : "r"(addr))
#define LDMATRIX_X4_T(r0, r1, r2, r3, addr) \
    asm volatile("ldmatrix.sync.aligned.m8n8.x4.trans.shared.b16 {%0,%1,%2,%3}, [%4];" \
                 : "=r"(r0), "=r"(r1), "=r"(r2), "=r"(r3) : "r"(addr))

#define MMA_FP16(c0, c1, c2, c3, a0, a1, a2, a3, b0, b1) \
    asm volatile("mma.sync.aligned.m16n8k16.row.col.f32.f16.f16.f32 " \
                 "{%0,%1,%2,%3}, {%4,%5,%6,%7}, {%8,%9}, {%0,%1,%2,%3};" \
                 : "+f"(c0), "+f"(c1), "+f"(c2), "+f"(c3) \
                 : "r"(a0), "r"(a1), "r"(a2), "r"(a3), "r"(b0), "r"(b1))

__device__ __forceinline__ uint32_t pack2h(__half x, __half y) {
    return (uint32_t)__half_as_ushort(x) |
           ((uint32_t)__half_as_ushort(y) << 16);
}

// ---------------------------------------------------------------------------
// LayerNorm row -> fp16 (device helper, 256 threads)
// ---------------------------------------------------------------------------
__device__ __forceinline__ void layernorm_row(
    const float* __restrict__ x, const float* __restrict__ g,
    const float* __restrict__ be, __half* __restrict__ o, int row,
    float* sm1, float* sm2)
{
    const int tid = threadIdx.x;
    const float4 v = *(const float4*)(x + (size_t)row * DMODEL + tid * 4);

    float s1 = v.x + v.y + v.z + v.w;
    float s2 = v.x * v.x + v.y * v.y + v.z * v.z + v.w * v.w;
    #pragma unroll
    for (int off = 16; off > 0; off >>= 1) {
        s1 += __shfl_xor_sync(0xffffffffu, s1, off);
        s2 += __shfl_xor_sync(0xffffffffu, s2, off);
    }
    const int w = tid >> 5, l = tid & 31;
    if (l == 0) { sm1[w] = s1; sm2[w] = s2; }
    __syncthreads();
    if (w == 0) {
        s1 = (l < 8) ? sm1[l] : 0.f;
        s2 = (l < 8) ? sm2[l] : 0.f;
        #pragma unroll
        for (int off = 4; off > 0; off >>= 1) {
            s1 += __shfl_xor_sync(0xffffffffu, s1, off);
            s2 += __shfl_xor_sync(0xffffffffu, s2, off);
        }
        if (l == 0) { sm1[0] = s1; sm2[0] = s2; }
    }
    __syncthreads();

    const float mu  = sm1[0] * (1.f / DMODEL);
    const float var = sm2[0] * (1.f / DMODEL) - mu * mu;
    const float inv = rsqrtf(var + 1e-5f);

    const float4 gv = *(const float4*)(g  + tid * 4);
    const float4 bv = *(const float4*)(be + tid * 4);
    __align__(8) __half h4[4];
    h4[0] = __float2half((v.x - mu) * inv * gv.x + bv.x);
    h4[1] = __float2half((v.y - mu) * inv * gv.y + bv.y);
    h4[2] = __float2half((v.z - mu) * inv * gv.z + bv.z);
    h4[3] = __float2half((v.w - mu) * inv * gv.w + bv.w);
    *(uint2*)(o + (size_t)row * DMODEL + tid * 4) = *(uint2*)h4;
}

__global__ void __launch_bounds__(256) layernorm_fp16_kernel(
    const float* __restrict__ x, const float* __restrict__ g,
    const float* __restrict__ be, __half* __restrict__ o)
{
    __shared__ float sm1[8], sm2[8];
    layernorm_row(x, g, be, o, blockIdx.x, sm1, sm2);
}

// ---------------------------------------------------------------------------
// FUSED prologue: blocks [0,12288) weight transpose; [12288,20480) LN1 rows
// ---------------------------------------------------------------------------
__global__ void __launch_bounds__(256) prologue_kernel(
    const float* __restrict__ Wq, const float* __restrict__ Wk,
    const float* __restrict__ Wv, const float* __restrict__ Wo,
    const float* __restrict__ W1, const float* __restrict__ W2,
    __half* __restrict__ wgt,
    const float* __restrict__ x, const float* __restrict__ g1,
    const float* __restrict__ be1, __half* __restrict__ ln)
{
    const int t = blockIdx.x;
    if (t >= 12288) {
        __shared__ float sm1[8], sm2[8];
        layernorm_row(x, g1, be1, ln, t - 12288, sm1, sm2);
        return;
    }

    const float* W; __half* o; int K, N, local; float scale = 1.f;
    if (t < 1024)      { W = Wq; o = wgt;           K = 1024; N = 1024; local = t;        scale = 0.125f; }
    else if (t < 2048) { W = Wk; o = wgt + 1 * MEG; K = 1024; N = 1024; local = t - 1024; }
    else if (t < 3072) { W = Wv; o = wgt + 2 * MEG; K = 1024; N = 1024; local = t - 2048; }
    else if (t < 4096) { W = Wo; o = wgt + 3 * MEG; K = 1024; N = 1024; local = t - 3072; }
    else if (t < 8192) { W = W1; o = wgt + 4 * MEG; K = 1024; N = 4096; local = t - 4096; }
    else               { W = W2; o = wgt + 8 * MEG; K = 4096; N = 1024; local = t - 8192; }

    const int ntn = N >> 5;
    const int n0 = (local % ntn) * 32;
    const int k0 = (local / ntn) * 32;

    __shared__ float tb[32][33];
    const int tx = threadIdx.x & 31, ty = threadIdx.x >> 5;
    #pragma unroll
    for (int j = 0; j < 32; j += 8)
        tb[ty + j][tx] = W[(size_t)(k0 + ty + j) * N + n0 + tx];
    __syncthreads();
    #pragma unroll
    for (int j = 0; j < 32; j += 8)
        o[(size_t)(n0 + ty + j) * K + k0 + tx] = __float2half(tb[tx][ty + j] * scale);
}

// ---------------------------------------------------------------------------
// fp16 single-pass mma.sync GEMM (R13 measured-optimal configuration)
// CTA tile 128x128, BK=64, 2-stage cp.async, 256 threads, 8 warps (4m x 2n),
// 73728 B smem -> 2 CTA/SM. ~88% of legacy-HMMA pipe floor.
// MODE: 0 = fp16 plain | 1 = f32 +res | 2 = fp16 relu(+bias) | 3 = f32 +bias +res
// ---------------------------------------------------------------------------
#define SM_STRIDE 72
#define SM_STRB   (SM_STRIDE * 2)
#define TILE_B    (128 * SM_STRB)          // 18432
#define STAGE_B   (2 * TILE_B)             // 36864

template<int MODE>
__global__ void __launch_bounds__(256) gemm_fp16_kernel(
    const __half* __restrict__ A, const __half* __restrict__ B,
    const float* __restrict__ bias, const float* __restrict__ res,
    float* __restrict__ Cf, __half* __restrict__ Oh, int M, int N, int K)
{
    const uint32_t sbase = smem_u32(smem_raw);
    const int tid = threadIdx.x;
    const int wid = tid >> 5, lid = tid & 31;
    const int warp_m = wid & 3;
    const int warp_n = wid >> 2;
    const int bm = blockIdx.y * 128;
    const int bn = blockIdx.x * 128;

    const int segN = K >> 6;
    const __half* Ag0 = A + (size_t)bm * K;
    const __half* Bg0 = B + (size_t)bn * K;

    auto load_chunk = [&](int c) {
        const uint32_t st = sbase + (c & 1) * STAGE_B;
        const int kk = c << 6;
        const __half* Ag = Ag0 + kk;
        const __half* Bg = Bg0 + kk;
        #pragma unroll
        for (int i = 0; i < 4; i++) {
            const int e = tid + 256 * i;       // 0..1023
            const int r = e >> 3;
            const int cch = e & 7;
            CP_ASYNC16(st + r * SM_STRB + cch * 16,
                       (const void*)(Ag + (size_t)r * K + cch * 8));
            CP_ASYNC16(st + TILE_B + r * SM_STRB + cch * 16,
                       (const void*)(Bg + (size_t)r * K + cch * 8));
        }
        CP_COMMIT();
    };

    float acc[2][8][4];
    #pragma unroll
    for (int mi = 0; mi < 2; mi++)
        #pragma unroll
        for (int ni = 0; ni < 8; ni++)
            #pragma unroll
            for (int q = 0; q < 4; q++) acc[mi][ni][q] = 0.f;

    const int a_row_off = (lid & 7) + ((lid >> 3) & 1) * 8;
    const int a_k_off   = ((lid >> 4) & 1) * 8;
    const int b_n_off   = (lid & 7) + ((lid >> 4) & 1) * 8;
    const int b_k_off   = ((lid >> 3) & 1) * 8;

    load_chunk(0);

    for (int c = 0; c < segN; c++) {
        if (c + 1 < segN) load_chunk(c + 1);
        if (c + 1 < segN) { CP_WAIT(1); } else { CP_WAIT(0); }
        __syncthreads();

        const uint32_t sA = sbase + (c & 1) * STAGE_B;
        const uint32_t sB = sA + TILE_B;

        #pragma unroll
        for (int k16 = 0; k16 < 64; k16 += 16) {
            uint32_t a[2][4];
            #pragma unroll
            for (int mi = 0; mi < 2; mi++) {
                const uint32_t roff =
                    (warp_m * 32 + mi * 16 + a_row_off) * SM_STRB + (k16 + a_k_off) * 2;
                LDMATRIX_X4(a[mi][0], a[mi][1], a[mi][2], a[mi][3], sA + roff);
            }
            uint32_t b[8][2];
            #pragma unroll
            for (int np = 0; np < 4; np++) {
                const uint32_t roff =
                    (warp_n * 64 + np * 16 + b_n_off) * SM_STRB + (k16 + b_k_off) * 2;
                uint32_t r0, r1, r2, r3;
                LDMATRIX_X4(r0, r1, r2, r3, sB + roff);
                b[2 * np][0] = r0; b[2 * np][1] = r1;
                b[2 * np + 1][0] = r2; b[2 * np + 1][1] = r3;
            }
            #pragma unroll
            for (int mi = 0; mi < 2; mi++)
                #pragma unroll
                for (int ni = 0; ni < 8; ni++)
                    MMA_FP16(acc[mi][ni][0], acc[mi][ni][1],
                             acc[mi][ni][2], acc[mi][ni][3],
                             a[mi][0], a[mi][1], a[mi][2], a[mi][3],
                             b[ni][0], b[ni][1]);
        }
        __syncthreads();
    }

    const int lr = lid >> 2;
    const int lc = (lid & 3) * 2;
    #pragma unroll
    for (int mi = 0; mi < 2; mi++) {
        #pragma unroll
        for (int ni = 0; ni < 8; ni++) {
            const int col = bn + warp_n * 64 + ni * 8 + lc;
            #pragma unroll
            for (int half = 0; half < 2; half++) {
                const int row = bm + warp_m * 32 + mi * 16 + lr + half * 8;
                const size_t off = (size_t)row * N + col;
                float v0 = acc[mi][ni][2 * half];
                float v1 = acc[mi][ni][2 * half + 1];
                if (MODE == 0) {
                    *(uint32_t*)(Oh + off) =
                        pack2h(__float2half(v0), __float2half(v1));
                } else if (MODE == 2) {
                    v0 = fmaxf(v0 + bias[col], 0.f);
                    v1 = fmaxf(v1 + bias[col + 1], 0.f);
                    *(uint32_t*)(Oh + off) =
                        pack2h(__float2half(v0), __float2half(v1));
                } else {
                    if (MODE == 3) { v0 += bias[col]; v1 += bias[col + 1]; }
                    const float2 rr = *(const float2*)(res + off);
                    v0 += rr.x; v1 += rr.y;
                    *(float2*)(Cf + off) = make_float2(v0, v1);
                }
            }
        }
    }
}

// ---------------------------------------------------------------------------
// fp16 tensor-core causal flash attention (R13 version: LPT ordering,
// folded Q-scale, double-buffered K/V)
// ---------------------------------------------------------------------------
#define ATT_STR  72
#define ATT_STRB (ATT_STR * 2)
#define ATT_Q_B  (128 * ATT_STRB)
#define ATT_KV_B (64 * ATT_STRB)
#define ATT_ST_B (2 * ATT_KV_B)

__global__ void __launch_bounds__(256) attention_fp16_kernel(
    const __half* __restrict__ QKV, __half* __restrict__ O)
{
    const uint32_t sbase = smem_u32(smem_raw);
    const uint32_t sQ = sbase;

    const int qt = (int)gridDim.x - 1 - (int)blockIdx.x;   // heavy tiles first
    const int bh = blockIdx.y;
    const int b  = bh >> 4;
    const int h  = bh & 15;
    const int q0 = qt * 128;
    const size_t rowbase = (size_t)b * SS;

    const int tid = threadIdx.x;
    const int w   = tid >> 5;
    const int lid = tid & 31;
    const int lr  = lid >> 2;
    const int lq  = lid & 3;

    const int a_row_off = (lid & 7) + ((lid >> 3) & 1) * 8;
    const int a_k_off   = ((lid >> 4) & 1) * 8;
    const int b_n_off   = (lid & 7) + ((lid >> 4) & 1) * 8;
    const int b_k_off   = ((lid >> 3) & 1) * 8;
    const int v_row_off = (lid & 7) + ((lid >> 3) & 1) * 8;
    const int v_col_off = ((lid >> 4) & 1) * 8;

    // Q load: pure cp.async (Wq pre-scaled by 0.125)
    {
        const size_t qcol = (size_t)h * DK;
        #pragma unroll
        for (int i = 0; i < 4; i++) {
            const int e = tid + 256 * i;
            const int r = e >> 3;
            const int c = e & 7;
            CP_ASYNC16(sQ + r * ATT_STRB + c * 16,
                       (const void*)(QKV + (rowbase + q0 + r) * QKVN + qcol + c * 8));
        }
        CP_COMMIT();
    }

    auto kv_load = [&](int kt) {
        const uint32_t st = sbase + ATT_Q_B + (kt & 1) * ATT_ST_B;
        const size_t kcol = 1024 + (size_t)h * DK;
        const size_t vcol = 2048 + (size_t)h * DK;
        #pragma unroll
        for (int i = 0; i < 2; i++) {
            const int e = tid + 256 * i;
            const int r = e >> 3;
            const int c = e & 7;
            const size_t grow = (rowbase + kt * 64 + r) * QKVN;
            const uint32_t sm = r * ATT_STRB + c * 16;
            CP_ASYNC16(st + sm,            (const void*)(QKV + grow + kcol + c * 8));
            CP_ASYNC16(st + ATT_KV_B + sm, (const void*)(QKV + grow + vcol + c * 8));
        }
        CP_COMMIT();
    };

    float m0 = -1e30f, m1 = -1e30f, l0 = 0.f, l1 = 0.f;
    float o[8][4];
    #pragma unroll
    for (int ni = 0; ni < 8; ni++)
        #pragma unroll
        for (int q = 0; q < 4; q++) o[ni][q] = 0.f;

    const int NT = 2 * qt + 2;
    kv_load(0);

    for (int kt = 0; kt < NT; kt++) {
        if (kt + 1 < NT) kv_load(kt + 1);
        if (kt + 1 < NT) { CP_WAIT(1); } else { CP_WAIT(0); }
        __syncthreads();

        const int wrow_min = q0 + w * 16;
        if (64 * kt <= wrow_min + 15) {
            const uint32_t sK = sbase + ATT_Q_B + (kt & 1) * ATT_ST_B;
            const uint32_t sV = sK + ATT_KV_B;

            float s[8][4];
            #pragma unroll
            for (int ni = 0; ni < 8; ni++)
                #pragma unroll
                for (int q = 0; q < 4; q++) s[ni][q] = 0.f;

            #pragma unroll
            for (int k16 = 0; k16 < 64; k16 += 16) {
                uint32_t a0, a1, a2, a3;
                LDMATRIX_X4(a0, a1, a2, a3,
                    sQ + (w * 16 + a_row_off) * ATT_STRB + (k16 + a_k_off) * 2);
                uint32_t bb[8][2];
                #pragma unroll
                for (int np = 0; np < 4; np++) {
                    uint32_t r0, r1, r2, r3;
                    LDMATRIX_X4(r0, r1, r2, r3,
                        sK + (np * 16 + b_n_off) * ATT_STRB + (k16 + b_k_off) * 2);
                    bb[2 * np][0] = r0; bb[2 * np][1] = r1;
                    bb[2 * np + 1][0] = r2; bb[2 * np + 1][1] = r3;
                }
                #pragma unroll
                for (int ni = 0; ni < 8; ni++)
                    MMA_FP16(s[ni][0], s[ni][1], s[ni][2], s[ni][3],
                             a0, a1, a2, a3, bb[ni][0], bb[ni][1]);
            }

            if (64 * kt + 63 > wrow_min) {
                const int r0g = wrow_min + lr;
                const int r1g = r0g + 8;
                #pragma unroll
                for (int ni = 0; ni < 8; ni++) {
                    const int c0 = 64 * kt + ni * 8 + lq * 2;
                    if (c0 > r0g)     s[ni][0] = -1e30f;
                    if (c0 + 1 > r0g) s[ni][1] = -1e30f;
                    if (c0 > r1g)     s[ni][2] = -1e30f;
                    if (c0 + 1 > r1g) s[ni][3] = -1e30f;
                }
            }

            float mt0 = -1e30f, mt1 = -1e30f;
            #pragma unroll
            for (int ni = 0; ni < 8; ni++) {
                mt0 = fmaxf(mt0, fmaxf(s[ni][0], s[ni][1]));
                mt1 = fmaxf(mt1, fmaxf(s[ni][2], s[ni][3]));
            }
            mt0 = fmaxf(mt0, __shfl_xor_sync(0xffffffffu, mt0, 1));
            mt0 = fmaxf(mt0, __shfl_xor_sync(0xffffffffu, mt0, 2));
            mt1 = fmaxf(mt1, __shfl_xor_sync(0xffffffffu, mt1, 1));
            mt1 = fmaxf(mt1, __shfl_xor_sync(0xffffffffu, mt1, 2));
            const float mn0 = fmaxf(m0, mt0), mn1 = fmaxf(m1, mt1);
            const float cr0 = __expf(m0 - mn0), cr1 = __expf(m1 - mn1);
            float rs0 = 0.f, rs1 = 0.f;
            #pragma unroll
            for (int ni = 0; ni < 8; ni++) {
                s[ni][0] = __expf(s[ni][0] - mn0); rs0 += s[ni][0];
                s[ni][1] = __expf(s[ni][1] - mn0); rs0 += s[ni][1];
                s[ni][2] = __expf(s[ni][2] - mn1); rs1 += s[ni][2];
                s[ni][3] = __expf(s[ni][3] - mn1); rs1 += s[ni][3];
            }
            rs0 += __shfl_xor_sync(0xffffffffu, rs0, 1);
            rs0 += __shfl_xor_sync(0xffffffffu, rs0, 2);
            rs1 += __shfl_xor_sync(0xffffffffu, rs1, 1);
            rs1 += __shfl_xor_sync(0xffffffffu, rs1, 2);
            l0 = l0 * cr0 + rs0;  l1 = l1 * cr1 + rs1;
            m0 = mn0;  m1 = mn1;
            #pragma unroll
            for (int ni = 0; ni < 8; ni++) {
                o[ni][0] *= cr0; o[ni][1] *= cr0;
                o[ni][2] *= cr1; o[ni][3] *= cr1;
            }

            #pragma unroll
            for (int j = 0; j < 4; j++) {
                const int t0 = 2 * j, t1 = 2 * j + 1;
                const uint32_t a0 = pack2h(__float2half(s[t0][0]), __float2half(s[t0][1]));
                const uint32_t a1 = pack2h(__float2half(s[t0][2]), __float2half(s[t0][3]));
                const uint32_t a2 = pack2h(__float2half(s[t1][0]), __float2half(s[t1][1]));
                const uint32_t a3 = pack2h(__float2half(s[t1][2]), __float2half(s[t1][3]));
                #pragma unroll
                for (int np = 0; np < 4; np++) {
                    uint32_t b0, b1, b2, b3;
                    LDMATRIX_X4_T(b0, b1, b2, b3,
                        sV + (j * 16 + v_row_off) * ATT_STRB + (np * 16 + v_col_off) * 2);
                    MMA_FP16(o[2*np][0], o[2*np][1], o[2*np][2], o[2*np][3],
                             a0, a1, a2, a3, b0, b1);
                    MMA_FP16(o[2*np+1][0], o[2*np+1][1], o[2*np+1][2], o[2*np+1][3],
                             a0, a1, a2, a3, b2, b3);
                }
            }
        }
        __syncthreads();
    }

    const float inv0 = 1.f / l0, inv1 = 1.f / l1;
    #pragma unroll
    for (int ni = 0; ni < 8; ni++) {
        const int col = h * DK + ni * 8 + lq * 2;
        {
            const size_t off = (rowbase + q0 + w * 16 + lr) * DMODEL + col;
            *(uint32_t*)(O + off) = pack2h(__float2half(o[ni][0] * inv0),
                                           __float2half(o[ni][1] * inv0));
        }
        {
            const size_t off = (rowbase + q0 + w * 16 + lr + 8) * DMODEL + col;
            *(uint32_t*)(O + off) = pack2h(__float2half(o[ni][2] * inv1),
                                           __float2half(o[ni][3] * inv1));
        }
    }
}

// ---------------------------------------------------------------------------
// Launch
// ---------------------------------------------------------------------------
extern "C" void kernel_launch(void* const* d_in, const int* in_sizes, int n_in,
                              void* d_out, int out_size)
{
    const float* x   = (const float*)d_in[0];
    const float* Wq  = (const float*)d_in[1];
    const float* Wk  = (const float*)d_in[2];
    const float* Wv  = (const float*)d_in[3];
    const float* Wo  = (const float*)d_in[4];
    const float* W1  = (const float*)d_in[5];
    const float* b1  = (const float*)d_in[6];
    const float* W2  = (const float*)d_in[7];
    const float* b2  = (const float*)d_in[8];
    const float* g1  = (const float*)d_in[9];
    const float* be1 = (const float*)d_in[10];
    const float* g2  = (const float*)d_in[11];
    const float* be2 = (const float*)d_in[12];
    float* out = (float*)d_out;

    float *x2;
    __half *ln, *att, *qkv, *ff, *wgt;
    cudaGetSymbolAddress((void**)&x2,  g_x2);
    cudaGetSymbolAddress((void**)&ln,  g_ln);
    cudaGetSymbolAddress((void**)&att, g_att);
    cudaGetSymbolAddress((void**)&qkv, g_qkv);
    cudaGetSymbolAddress((void**)&ff,  g_ff);
    cudaGetSymbolAddress((void**)&wgt, g_w);

    const int GEMM_SMEM = 2 * STAGE_B;                 // 73728
    cudaFuncSetAttribute(gemm_fp16_kernel<0>, cudaFuncAttributeMaxDynamicSharedMemorySize, GEMM_SMEM);
    cudaFuncSetAttribute(gemm_fp16_kernel<1>, cudaFuncAttributeMaxDynamicSharedMemorySize, GEMM_SMEM);
    cudaFuncSetAttribute(gemm_fp16_kernel<2>, cudaFuncAttributeMaxDynamicSharedMemorySize, GEMM_SMEM);
    cudaFuncSetAttribute(gemm_fp16_kernel<3>, cudaFuncAttributeMaxDynamicSharedMemorySize, GEMM_SMEM);
    const int ATTN_SMEM = ATT_Q_B + 2 * ATT_ST_B;      // 55296
    cudaFuncSetAttribute(attention_fp16_kernel, cudaFuncAttributeMaxDynamicSharedMemorySize, ATTN_SMEM);

    // 0) fused prologue: ALL weight transposes + LN1 in ONE launch
    prologue_kernel<<<12288 + MROWS, 256>>>(Wq, Wk, Wv, Wo, W1, W2, wgt,
                                            x, g1, be1, ln);

    // 1) fused QKV projection -> fp16 [row][3072]
    {
        dim3 grid(QKVN / 128, MROWS / 128);
        gemm_fp16_kernel<0><<<grid, 256, GEMM_SMEM>>>(ln, wgt,
            nullptr, nullptr, nullptr, qkv, MROWS, QKVN, DMODEL);
    }

    // 2) causal attention -> att (fp16), heavy q-tiles scheduled first
    {
        dim3 grid(SS / 128, BB * NHEADS);
        attention_fp16_kernel<<<grid, 256, ATTN_SMEM>>>(qkv, att);
    }

    // 3) output projection + residual(x) -> x2 (f32)
    {
        dim3 grid(DMODEL / 128, MROWS / 128);
        gemm_fp16_kernel<1><<<grid, 256, GEMM_SMEM>>>(att, wgt + 3 * MEG,
            nullptr, x, x2, nullptr, MROWS, DMODEL, DMODEL);
    }

    // 4) LN2 -> fp16
    layernorm_fp16_kernel<<<MROWS, 256>>>(x2, g2, be2, ln);

    // 5) FFN1: relu(h2 @ W1 + b1) -> fp16
    {
        dim3 grid(DFF / 128, MROWS / 128);
        gemm_fp16_kernel<2><<<grid, 256, GEMM_SMEM>>>(ln, wgt + 4 * MEG,
            b1, nullptr, nullptr, ff, MROWS, DFF, DMODEL);
    }

    // 6) FFN2: ff @ W2 + b2 + x2 -> out
    {
        dim3 grid(DMODEL / 128, MROWS / 128);
        gemm_fp16_kernel<3><<<grid, 256, GEMM_SMEM>>>(ff, wgt + 8 * MEG,
            b2, x2, out, nullptr, MROWS, DMODEL, DFF);
    }
}